// round 1
// baseline (speedup 1.0000x reference)
#include <cuda_runtime.h>
#include <math.h>

#define BATCH 8
#define SEQ   16
#define NH    16
#define HD    128
#define DIM   2048
#define DIM3  6144
#define CACHE 4096
#define TTOT  4112
#define NTOK  128

// output layout: [ out (128x2048) | kh (8,16,4112,128) | vh (...) ]
#define KH_OFF (NTOK*DIM)
#define KH_ELEMS (BATCH*NH*TTOT*HD)
#define VH_OFF (KH_OFF + KH_ELEMS)

typedef unsigned long long u64;

__device__ float g_qkv[NTOK * DIM3];   // 3 MB scratch
__device__ float g_ctx[NTOK * DIM];    // 1 MB scratch

// ---------- packed f32x2 helpers (sm_103a) ----------
__device__ __forceinline__ u64 pk2(float lo, float hi) {
    u64 r; asm("mov.b64 %0, {%1, %2};" : "=l"(r) : "f"(lo), "f"(hi)); return r;
}
__device__ __forceinline__ void upk2(u64 v, float& lo, float& hi) {
    asm("mov.b64 {%0, %1}, %2;" : "=f"(lo), "=f"(hi) : "l"(v));
}
__device__ __forceinline__ u64 ffma2(u64 a, u64 b, u64 c) {
    u64 d; asm("fma.rn.f32x2 %0, %1, %2, %3;" : "=l"(d) : "l"(a), "l"(b), "l"(c)); return d;
}
__device__ __forceinline__ u64 fmul2(u64 a, u64 b) {
    u64 d; asm("mul.rn.f32x2 %0, %1, %2;" : "=l"(d) : "l"(a), "l"(b)); return d;
}

// ---------- GEMM: C[M,N] = A[M,K] @ Bw[K,N] + bias ----------
// BM=32, BK=16, 256 threads, thread tile 2 rows x TN cols (TN = BN/16),
// columns interleaved (n = tx*2 + j*32) for conflict-free LDS.64 of B pairs.
template<int BN>
__device__ __forceinline__ void gemm_body(const float* __restrict__ A,
                                          const float* __restrict__ Bw,
                                          const float* __restrict__ bias,
                                          float* __restrict__ C,
                                          int N, int K)
{
    constexpr int BM = 32, BK = 16;
    constexpr int TN2 = BN / 32;           // u64 pairs per thread (4 or 2)
    __shared__ float As[BK][BM];
    __shared__ float Bs[BK][BN];
    int tid = threadIdx.x;
    int m0 = blockIdx.y * BM;
    int n0 = blockIdx.x * BN;
    int tx = tid & 15;
    int ty = tid >> 4;

    u64 acc[2][TN2];
    #pragma unroll
    for (int i = 0; i < 2; i++)
        #pragma unroll
        for (int j = 0; j < TN2; j++) acc[i][j] = 0ULL;

    for (int k0 = 0; k0 < K; k0 += BK) {
        if (tid < 128) {
            int am = tid >> 2, ak = (tid & 3) << 2;
            float4 av = *(const float4*)&A[(m0 + am) * K + k0 + ak];
            As[ak+0][am] = av.x; As[ak+1][am] = av.y;
            As[ak+2][am] = av.z; As[ak+3][am] = av.w;
        }
        #pragma unroll
        for (int f = tid; f < BK * BN / 4; f += 256) {
            int bk = f / (BN/4), bn = f % (BN/4);
            *(float4*)&Bs[bk][bn*4] = *(const float4*)&Bw[(k0 + bk) * N + n0 + bn*4];
        }
        __syncthreads();
        #pragma unroll
        for (int k = 0; k < BK; k++) {
            float a0 = As[k][ty*2], a1 = As[k][ty*2+1];
            u64 a0p = pk2(a0, a0), a1p = pk2(a1, a1);
            #pragma unroll
            for (int j = 0; j < TN2; j++) {
                u64 bb = *(const u64*)&Bs[k][tx*2 + j*32];
                acc[0][j] = ffma2(a0p, bb, acc[0][j]);
                acc[1][j] = ffma2(a1p, bb, acc[1][j]);
            }
        }
        __syncthreads();
    }
    #pragma unroll
    for (int i = 0; i < 2; i++) {
        int m = m0 + ty*2 + i;
        #pragma unroll
        for (int j = 0; j < TN2; j++) {
            int n = n0 + tx*2 + j*32;
            float lo, hi; upk2(acc[i][j], lo, hi);
            float2 w; w.x = lo + bias[n]; w.y = hi + bias[n+1];
            *(float2*)&C[m * N + n] = w;
        }
    }
}

__global__ void __launch_bounds__(256)
qkv_gemm(const float* __restrict__ x, const float* __restrict__ W,
         const float* __restrict__ bias)
{
    gemm_body<128>(x, W, bias, g_qkv, DIM3, DIM);
}

__global__ void __launch_bounds__(256)
proj_gemm(const float* __restrict__ W, const float* __restrict__ bias,
          float* __restrict__ out)
{
    gemm_body<64>(g_ctx, W, bias, out, DIM, DIM);
}

// ---------- fused flash attention + KV-concat writeout ----------
// One block per (b,h). 256 threads = 16 queries (s = tid>>4) x 16 d-groups
// (dg = tid&15; d chunks [4dg..4dg+3] and [64+4dg..64+4dg+3]).
// Each 32-key tile: stream K/V gmem->smem, write to kh/vh output, compute
// scores with f32x2 + half-warp butterfly reduce, online softmax, ctx accum.
__global__ void __launch_bounds__(256)
attn_kernel(const float* __restrict__ kc, const float* __restrict__ vc,
            float* __restrict__ out)
{
    __shared__ float Kt[32][HD];
    __shared__ float Vt[32][HD];
    int h = blockIdx.x, b = blockIdx.y;
    int tid = threadIdx.x;
    int s = tid >> 4, dg = tid & 15;

    const float* qbase = &g_qkv[(b*SEQ + s)*DIM3 + h*HD];
    ulonglong2 qa = *(const ulonglong2*)&qbase[4*dg];
    ulonglong2 qb = *(const ulonglong2*)&qbase[64 + 4*dg];
    u64 qp0 = qa.x, qp1 = qa.y, qp2 = qb.x, qp3 = qb.y;

    u64 ac0 = 0ULL, ac1 = 0ULL, ac2 = 0ULL, ac3 = 0ULL;
    float m_r = -INFINITY, l_r = 0.f;
    const float SCALE = 0.08838834764831845f;  // 1/sqrt(128)

    const float* kcb = &kc[(size_t)(b*NH + h) * CACHE * HD];
    const float* vcb = &vc[(size_t)(b*NH + h) * CACHE * HD];
    float* khout = &out[KH_OFF + (b*NH + h) * TTOT * HD];
    float* vhout = &out[VH_OFF + (b*NH + h) * TTOT * HD];

    for (int tile = 0; tile < 129; tile++) {
        int t0 = tile * 32;
        int rows = min(32, TTOT - t0);
        #pragma unroll
        for (int i = 0; i < 4; i++) {
            int idx = tid + i * 256;
            int r = idx >> 5, c = idx & 31;
            int t = t0 + r;
            if (r < rows) {
                float4 kv, vv;
                if (t < CACHE) {
                    kv = *(const float4*)&kcb[t*HD + c*4];
                    vv = *(const float4*)&vcb[t*HD + c*4];
                } else {
                    int tok = b*SEQ + (t - CACHE);
                    kv = *(const float4*)&g_qkv[tok*DIM3 +   DIM + h*HD + c*4];
                    vv = *(const float4*)&g_qkv[tok*DIM3 + 2*DIM + h*HD + c*4];
                }
                *(float4*)&Kt[r][c*4] = kv;
                *(float4*)&Vt[r][c*4] = vv;
                *(float4*)&khout[t*HD + c*4] = kv;
                *(float4*)&vhout[t*HD + c*4] = vv;
            }
        }
        __syncthreads();

        float sc[32];
        #pragma unroll
        for (int tt = 0; tt < 32; tt++) {
            ulonglong2 k0 = *(const ulonglong2*)&Kt[tt][4*dg];
            ulonglong2 k1 = *(const ulonglong2*)&Kt[tt][64 + 4*dg];
            u64 p2 = ffma2(qp0, k0.x, fmul2(qp1, k0.y));
            p2 = ffma2(qp2, k1.x, p2);
            p2 = ffma2(qp3, k1.y, p2);
            float lo, hi; upk2(p2, lo, hi);
            float part = lo + hi;
            part += __shfl_xor_sync(0xffffffffu, part, 1);
            part += __shfl_xor_sync(0xffffffffu, part, 2);
            part += __shfl_xor_sync(0xffffffffu, part, 4);
            part += __shfl_xor_sync(0xffffffffu, part, 8);
            sc[tt] = part * SCALE;
        }
        if (tile == 128) {
            #pragma unroll
            for (int tt = 0; tt < 32; tt++)
                if (t0 + tt > CACHE + s) sc[tt] = -INFINITY;
        }

        float tmax = m_r;
        #pragma unroll
        for (int tt = 0; tt < 32; tt++) tmax = fmaxf(tmax, sc[tt]);
        float corr = __expf(m_r - tmax);
        m_r = tmax;
        float lsum = 0.f;
        #pragma unroll
        for (int tt = 0; tt < 32; tt++) {
            float e = __expf(sc[tt] - tmax);
            sc[tt] = e;
            lsum += e;
        }
        l_r = l_r * corr + lsum;
        u64 corr2 = pk2(corr, corr);
        ac0 = fmul2(ac0, corr2); ac1 = fmul2(ac1, corr2);
        ac2 = fmul2(ac2, corr2); ac3 = fmul2(ac3, corr2);

        #pragma unroll
        for (int tt = 0; tt < 32; tt++) {
            u64 p2 = pk2(sc[tt], sc[tt]);
            ulonglong2 v0 = *(const ulonglong2*)&Vt[tt][4*dg];
            ulonglong2 v1 = *(const ulonglong2*)&Vt[tt][64 + 4*dg];
            ac0 = ffma2(p2, v0.x, ac0);
            ac1 = ffma2(p2, v0.y, ac1);
            ac2 = ffma2(p2, v1.x, ac2);
            ac3 = ffma2(p2, v1.y, ac3);
        }
        __syncthreads();
    }

    float inv = 1.0f / l_r;
    float o[8];
    upk2(ac0, o[0], o[1]); upk2(ac1, o[2], o[3]);
    upk2(ac2, o[4], o[5]); upk2(ac3, o[6], o[7]);
    float* cb = &g_ctx[(b*SEQ + s)*DIM + h*HD];
    float4 w0, w1;
    w0.x = o[0]*inv; w0.y = o[1]*inv; w0.z = o[2]*inv; w0.w = o[3]*inv;
    w1.x = o[4]*inv; w1.y = o[5]*inv; w1.z = o[6]*inv; w1.w = o[7]*inv;
    *(float4*)&cb[4*dg] = w0;
    *(float4*)&cb[64 + 4*dg] = w1;
}

extern "C" void kernel_launch(void* const* d_in, const int* in_sizes, int n_in,
                              void* d_out, int out_size)
{
    const float* x      = (const float*)d_in[0];
    const float* kc     = (const float*)d_in[1];
    const float* vc     = (const float*)d_in[2];
    const float* W_attn = (const float*)d_in[3];
    const float* b_attn = (const float*)d_in[4];
    const float* W_proj = (const float*)d_in[5];
    const float* b_proj = (const float*)d_in[6];
    float* out = (float*)d_out;

    qkv_gemm<<<dim3(DIM3/128, NTOK/32), 256>>>(x, W_attn, b_attn);
    attn_kernel<<<dim3(NH, BATCH), 256>>>(kc, vc, out);
    proj_gemm<<<dim3(DIM/64, NTOK/32), 256>>>(W_proj, b_proj, out);
}

// round 3
// speedup vs baseline: 1.8236x; 1.8236x over previous
#include <cuda_runtime.h>
#include <math.h>

#define BATCH 8
#define SEQ   16
#define NH    16
#define HD    128
#define DIM   2048
#define DIM3  6144
#define CACHE 4096
#define TTOT  4112
#define NTOK  128
#define NSPL  4

#define KH_OFF (NTOK*DIM)
#define KH_ELEMS (BATCH*NH*TTOT*HD)
#define VH_OFF (KH_OFF + KH_ELEMS)

typedef unsigned long long u64;

__device__ float g_qkv[NTOK * DIM3];            // 3 MB
__device__ float g_ctx[NTOK * DIM];             // 1 MB
__device__ float g_part[4 * NTOK * DIM3];       // 12.6 MB split-K partials
__device__ float g_pacc[BATCH*NH*NSPL*SEQ*HD];  // 4 MB attn partial ctx
__device__ float g_pm[BATCH*NH*NSPL*SEQ];
__device__ float g_pl[BATCH*NH*NSPL*SEQ];

// ---------- packed f32x2 helpers (sm_103a) ----------
__device__ __forceinline__ u64 pk2(float lo, float hi) {
    u64 r; asm("mov.b64 %0, {%1, %2};" : "=l"(r) : "f"(lo), "f"(hi)); return r;
}
__device__ __forceinline__ void upk2(u64 v, float& lo, float& hi) {
    asm("mov.b64 {%0, %1}, %2;" : "=f"(lo), "=f"(hi) : "l"(v));
}
__device__ __forceinline__ u64 ffma2(u64 a, u64 b, u64 c) {
    u64 d; asm("fma.rn.f32x2 %0, %1, %2, %3;" : "=l"(d) : "l"(a), "l"(b), "l"(c)); return d;
}
__device__ __forceinline__ u64 fmul2(u64 a, u64 b) {
    u64 d; asm("mul.rn.f32x2 %0, %1, %2;" : "=l"(d) : "l"(a), "l"(b)); return d;
}

// ---------- split-K GEMM: Cpart[split][128][N] = A[128,Kslice] @ Bw[Kslice,N] ----------
// BM=128 (all rows), BN=64, BK=16, 256 threads, thread tile 8m x 4n.
// m-dim paired into f32x2: a-pairs are native u64 LDS from As[k][m], only 4 pk2/k.
template<int KSLICE>
__global__ void __launch_bounds__(256)
gemm_splitk(const float* __restrict__ A, const float* __restrict__ Bw,
            float* __restrict__ Cpart, int N)
{
    constexpr int BN = 64, BK = 16;
    __shared__ float As[BK][NTOK];
    __shared__ float Bs[BK][BN];
    int tid = threadIdx.x;
    int n0 = blockIdx.x * BN;
    int kbase = blockIdx.y * KSLICE;
    int K = gridDim.y * KSLICE;
    int tx = tid & 15, ty = tid >> 4;

    u64 acc[4][4];
    #pragma unroll
    for (int i = 0; i < 4; i++)
        #pragma unroll
        for (int j = 0; j < 4; j++) acc[i][j] = 0ULL;

    for (int k0 = kbase; k0 < kbase + KSLICE; k0 += BK) {
        #pragma unroll
        for (int j = 0; j < 2; j++) {
            int lin = tid + j * 256;
            int am = lin & 127, k4 = (lin >> 7) * 4;
            float4 av = *(const float4*)&A[am * K + k0 + k4];
            As[k4+0][am] = av.x; As[k4+1][am] = av.y;
            As[k4+2][am] = av.z; As[k4+3][am] = av.w;
        }
        {
            int bk = tid >> 4, bn = (tid & 15) * 4;
            *(float4*)&Bs[bk][bn] = *(const float4*)&Bw[(k0 + bk) * N + n0 + bn];
        }
        __syncthreads();
        #pragma unroll
        for (int k = 0; k < BK; k++) {
            ulonglong2 a01 = *(const ulonglong2*)&As[k][ty*8];
            ulonglong2 a23 = *(const ulonglong2*)&As[k][ty*8 + 4];
            float4 bf = *(const float4*)&Bs[k][tx*4];
            u64 b0 = pk2(bf.x, bf.x), b1 = pk2(bf.y, bf.y);
            u64 b2 = pk2(bf.z, bf.z), b3 = pk2(bf.w, bf.w);
            acc[0][0] = ffma2(a01.x, b0, acc[0][0]);
            acc[0][1] = ffma2(a01.x, b1, acc[0][1]);
            acc[0][2] = ffma2(a01.x, b2, acc[0][2]);
            acc[0][3] = ffma2(a01.x, b3, acc[0][3]);
            acc[1][0] = ffma2(a01.y, b0, acc[1][0]);
            acc[1][1] = ffma2(a01.y, b1, acc[1][1]);
            acc[1][2] = ffma2(a01.y, b2, acc[1][2]);
            acc[1][3] = ffma2(a01.y, b3, acc[1][3]);
            acc[2][0] = ffma2(a23.x, b0, acc[2][0]);
            acc[2][1] = ffma2(a23.x, b1, acc[2][1]);
            acc[2][2] = ffma2(a23.x, b2, acc[2][2]);
            acc[2][3] = ffma2(a23.x, b3, acc[2][3]);
            acc[3][0] = ffma2(a23.y, b0, acc[3][0]);
            acc[3][1] = ffma2(a23.y, b1, acc[3][1]);
            acc[3][2] = ffma2(a23.y, b2, acc[3][2]);
            acc[3][3] = ffma2(a23.y, b3, acc[3][3]);
        }
        __syncthreads();
    }
    float* cp = Cpart + (size_t)blockIdx.y * NTOK * N;
    #pragma unroll
    for (int mp = 0; mp < 4; mp++) {
        float lo[4], hi[4];
        #pragma unroll
        for (int j = 0; j < 4; j++) upk2(acc[mp][j], lo[j], hi[j]);
        int m = ty * 8 + mp * 2;
        float4 w0 = {lo[0], lo[1], lo[2], lo[3]};
        float4 w1 = {hi[0], hi[1], hi[2], hi[3]};
        *(float4*)&cp[(m+0) * N + n0 + tx*4] = w0;
        *(float4*)&cp[(m+1) * N + n0 + tx*4] = w1;
    }
}

// ---------- split-K reduce: C[m][n] = bias[n] + sum_s Cpart[s][m][n] ----------
template<int NS>
__global__ void __launch_bounds__(256)
reduce_part(const float* __restrict__ Cpart, const float* __restrict__ bias,
            float* __restrict__ C, int N)
{
    int idx = blockIdx.x * 256 + threadIdx.x;     // one float4 each
    int n4 = N / 4;
    int m = idx / n4, n = (idx % n4) * 4;
    float4 s = *(const float4*)&bias[n];
    #pragma unroll
    for (int sp = 0; sp < NS; sp++) {
        float4 p = *(const float4*)&Cpart[(size_t)sp * NTOK * N + m * N + n];
        s.x += p.x; s.y += p.y; s.z += p.z; s.w += p.w;
    }
    *(float4*)&C[m * N + n] = s;
}

// ---------- split-KV flash attention + KV-concat writeout ----------
// grid (NSPL, NH, BATCH), 256 thr = 16 queries x 16 d-groups. Register-prefetch
// double buffering of 32-key tiles; partial (m,l,acc) to scratch.
__global__ void __launch_bounds__(256)
attn_split(const float* __restrict__ kc, const float* __restrict__ vc,
           float* __restrict__ out)
{
    __shared__ float Kt[32][HD];
    __shared__ float Vt[32][HD];
    int sp = blockIdx.x, h = blockIdx.y, b = blockIdx.z;
    int tid = threadIdx.x;
    int s = tid >> 4, dg = tid & 15;

    int tb = sp * 32;
    int te = (sp == NSPL - 1) ? 129 : tb + 32;

    const float* qbase = &g_qkv[(b*SEQ + s)*DIM3 + h*HD];
    ulonglong2 qa = *(const ulonglong2*)&qbase[4*dg];
    ulonglong2 qb = *(const ulonglong2*)&qbase[64 + 4*dg];
    u64 qp0 = qa.x, qp1 = qa.y, qp2 = qb.x, qp3 = qb.y;

    u64 ac0 = 0ULL, ac1 = 0ULL, ac2 = 0ULL, ac3 = 0ULL;
    float m_r = -INFINITY, l_r = 0.f;
    const float SCALE = 0.08838834764831845f;

    const float* kcb = &kc[(size_t)(b*NH + h) * CACHE * HD];
    const float* vcb = &vc[(size_t)(b*NH + h) * CACHE * HD];
    float* khout = &out[KH_OFF + (size_t)(b*NH + h) * TTOT * HD];
    float* vhout = &out[VH_OFF + (size_t)(b*NH + h) * TTOT * HD];

    float4 pk[4], pv[4];
    // prefetch first tile
    {
        int t0 = tb * 32;
        #pragma unroll
        for (int i = 0; i < 4; i++) {
            int idx = tid + i * 256;
            int r = idx >> 5, c = idx & 31;
            int t = t0 + r;
            if (t < TTOT) {
                if (t < CACHE) {
                    pk[i] = *(const float4*)&kcb[t*HD + c*4];
                    pv[i] = *(const float4*)&vcb[t*HD + c*4];
                } else {
                    int tok = b*SEQ + (t - CACHE);
                    pk[i] = *(const float4*)&g_qkv[tok*DIM3 +   DIM + h*HD + c*4];
                    pv[i] = *(const float4*)&g_qkv[tok*DIM3 + 2*DIM + h*HD + c*4];
                }
            }
        }
    }

    for (int tile = tb; tile < te; tile++) {
        int t0 = tile * 32;
        int rows = min(32, TTOT - t0);
        #pragma unroll
        for (int i = 0; i < 4; i++) {
            int idx = tid + i * 256;
            int r = idx >> 5, c = idx & 31;
            int t = t0 + r;
            if (r < rows) {
                *(float4*)&Kt[r][c*4] = pk[i];
                *(float4*)&Vt[r][c*4] = pv[i];
                *(float4*)&khout[t*HD + c*4] = pk[i];
                *(float4*)&vhout[t*HD + c*4] = pv[i];
            }
        }
        __syncthreads();

        // issue prefetch for next tile (overlaps with compute below)
        if (tile + 1 < te) {
            int nt0 = (tile + 1) * 32;
            #pragma unroll
            for (int i = 0; i < 4; i++) {
                int idx = tid + i * 256;
                int r = idx >> 5, c = idx & 31;
                int t = nt0 + r;
                if (t < TTOT) {
                    if (t < CACHE) {
                        pk[i] = *(const float4*)&kcb[t*HD + c*4];
                        pv[i] = *(const float4*)&vcb[t*HD + c*4];
                    } else {
                        int tok = b*SEQ + (t - CACHE);
                        pk[i] = *(const float4*)&g_qkv[tok*DIM3 +   DIM + h*HD + c*4];
                        pv[i] = *(const float4*)&g_qkv[tok*DIM3 + 2*DIM + h*HD + c*4];
                    }
                }
            }
        }

        float sc[32];
        #pragma unroll
        for (int tt = 0; tt < 32; tt++) {
            ulonglong2 k0 = *(const ulonglong2*)&Kt[tt][4*dg];
            ulonglong2 k1 = *(const ulonglong2*)&Kt[tt][64 + 4*dg];
            u64 p2 = ffma2(qp0, k0.x, fmul2(qp1, k0.y));
            p2 = ffma2(qp2, k1.x, p2);
            p2 = ffma2(qp3, k1.y, p2);
            float lo, hi; upk2(p2, lo, hi);
            float part = lo + hi;
            part += __shfl_xor_sync(0xffffffffu, part, 1);
            part += __shfl_xor_sync(0xffffffffu, part, 2);
            part += __shfl_xor_sync(0xffffffffu, part, 4);
            part += __shfl_xor_sync(0xffffffffu, part, 8);
            sc[tt] = part * SCALE;
        }
        if (tile == 128) {
            #pragma unroll
            for (int tt = 0; tt < 32; tt++)
                if (t0 + tt > CACHE + s) sc[tt] = -INFINITY;
        }

        float tmax = m_r;
        #pragma unroll
        for (int tt = 0; tt < 32; tt++) tmax = fmaxf(tmax, sc[tt]);
        float corr = __expf(m_r - tmax);
        m_r = tmax;
        float lsum = 0.f;
        #pragma unroll
        for (int tt = 0; tt < 32; tt++) {
            float e = __expf(sc[tt] - tmax);
            sc[tt] = e;
            lsum += e;
        }
        l_r = l_r * corr + lsum;
        u64 corr2 = pk2(corr, corr);
        ac0 = fmul2(ac0, corr2); ac1 = fmul2(ac1, corr2);
        ac2 = fmul2(ac2, corr2); ac3 = fmul2(ac3, corr2);

        #pragma unroll
        for (int tt = 0; tt < 32; tt++) {
            u64 p2 = pk2(sc[tt], sc[tt]);
            ulonglong2 v0 = *(const ulonglong2*)&Vt[tt][4*dg];
            ulonglong2 v1 = *(const ulonglong2*)&Vt[tt][64 + 4*dg];
            ac0 = ffma2(p2, v0.x, ac0);
            ac1 = ffma2(p2, v0.y, ac1);
            ac2 = ffma2(p2, v1.x, ac2);
            ac3 = ffma2(p2, v1.y, ac3);
        }
        __syncthreads();
    }

    // store partial (unnormalized acc + m,l)
    int pb = ((b*NH + h) * NSPL + sp) * SEQ + s;
    if (dg == 0) { g_pm[pb] = m_r; g_pl[pb] = l_r; }
    float o[8];
    upk2(ac0, o[0], o[1]); upk2(ac1, o[2], o[3]);
    upk2(ac2, o[4], o[5]); upk2(ac3, o[6], o[7]);
    float4 w0 = {o[0], o[1], o[2], o[3]};
    float4 w1 = {o[4], o[5], o[6], o[7]};
    *(float4*)&g_pacc[(size_t)pb * HD + 4*dg] = w0;
    *(float4*)&g_pacc[(size_t)pb * HD + 64 + 4*dg] = w1;
}

// ---------- combine split-KV partials -> g_ctx ----------
__global__ void __launch_bounds__(256)
attn_combine()
{
    int h = blockIdx.x, b = blockIdx.y;
    int tid = threadIdx.x;
    int s = tid >> 4, dg = tid & 15;
    int base = ((b*NH + h) * NSPL) * SEQ + s;

    float m[NSPL], l[NSPL];
    #pragma unroll
    for (int sp = 0; sp < NSPL; sp++) {
        m[sp] = g_pm[base + sp*SEQ];
        l[sp] = g_pl[base + sp*SEQ];
    }
    float M = m[0];
    #pragma unroll
    for (int sp = 1; sp < NSPL; sp++) M = fmaxf(M, m[sp]);
    float L = 0.f, w[NSPL];
    #pragma unroll
    for (int sp = 0; sp < NSPL; sp++) { w[sp] = __expf(m[sp] - M); L += w[sp] * l[sp]; }

    float o[8] = {0,0,0,0,0,0,0,0};
    #pragma unroll
    for (int sp = 0; sp < NSPL; sp++) {
        size_t pb = (size_t)(base + sp*SEQ) * HD;
        float4 a0 = *(const float4*)&g_pacc[pb + 4*dg];
        float4 a1 = *(const float4*)&g_pacc[pb + 64 + 4*dg];
        o[0] += w[sp]*a0.x; o[1] += w[sp]*a0.y; o[2] += w[sp]*a0.z; o[3] += w[sp]*a0.w;
        o[4] += w[sp]*a1.x; o[5] += w[sp]*a1.y; o[6] += w[sp]*a1.z; o[7] += w[sp]*a1.w;
    }
    float inv = 1.0f / L;
    float* cb = &g_ctx[(b*SEQ + s)*DIM + h*HD];
    float4 w0 = {o[0]*inv, o[1]*inv, o[2]*inv, o[3]*inv};
    float4 w1 = {o[4]*inv, o[5]*inv, o[6]*inv, o[7]*inv};
    *(float4*)&cb[4*dg] = w0;
    *(float4*)&cb[64 + 4*dg] = w1;
}

extern "C" void kernel_launch(void* const* d_in, const int* in_sizes, int n_in,
                              void* d_out, int out_size)
{
    const float* x      = (const float*)d_in[0];
    const float* kc     = (const float*)d_in[1];
    const float* vc     = (const float*)d_in[2];
    const float* W_attn = (const float*)d_in[3];
    const float* b_attn = (const float*)d_in[4];
    const float* W_proj = (const float*)d_in[5];
    const float* b_proj = (const float*)d_in[6];
    float* out = (float*)d_out;

    float *p_qkv, *p_ctx, *p_part;
    cudaGetSymbolAddress((void**)&p_qkv,  g_qkv);
    cudaGetSymbolAddress((void**)&p_ctx,  g_ctx);
    cudaGetSymbolAddress((void**)&p_part, g_part);

    // QKV: 128x2048 @ 2048x6144, split-K 4
    gemm_splitk<512><<<dim3(DIM3/64, 4), 256>>>(x, W_attn, p_part, DIM3);
    reduce_part<4><<<(NTOK*DIM3/4)/256, 256>>>(p_part, b_attn, p_qkv, DIM3);
    // attention, split-KV 4 + KV concat writeout
    attn_split<<<dim3(NSPL, NH, BATCH), 256>>>(kc, vc, out);
    attn_combine<<<dim3(NH, BATCH), 256>>>();
    // proj: 128x2048 @ 2048x2048, split-K 8
    gemm_splitk<256><<<dim3(DIM/64, 8), 256>>>(p_ctx, W_proj, p_part, DIM);
    reduce_part<8><<<(NTOK*DIM/4)/256, 256>>>(p_part, b_proj, out, DIM);
}